// round 8
// baseline (speedup 1.0000x reference)
#include <cuda_runtime.h>
#include <cuda_bf16.h>
#include <cstdint>
#include <cstring>

#define D_MODEL 2048
#define NE      64
#define TM      128
#define BK      32
#define NCHUNK  (D_MODEL / BK)   // 64
#define THREADS 512
#define SROW    28               // b32 stride per row; 112B rows -> conflict-free LDSM octets

// per-buffer tile layout (floats, relative to tile base)
#define T_XH 0
#define T_XM (T_XH + TM * SROW)      // 3584
#define T_XL (T_XM + TM * SROW)      // 7168
#define T_WH (T_XL + TM * SROW)      // 10752
#define T_WM (T_WH + NE * SROW)      // 12544
#define T_WL (T_WM + NE * SROW)      // 14336
#define TILE_FLOATS (T_WL + NE * SROW)   // 16128

#define BIAS  0
#define TILE0 64
#define SMEM_FLOATS (TILE0 + 2 * TILE_FLOATS)   // 32320
#define SMEM_BYTES  (SMEM_FLOATS * 4)           // 129280

#define LS        TILE0
#define LS_STRIDE 65

__device__ __forceinline__ uint32_t smem_u32(const void* p) {
    uint32_t a;
    asm("{ .reg .u64 t; cvta.to.shared.u64 t, %1; cvt.u32.u64 %0, t; }"
        : "=r"(a) : "l"(p));
    return a;
}

__device__ __forceinline__ uint32_t bf16pair(float lo, float hi) {
    __nv_bfloat162 p = __floats2bfloat162_rn(lo, hi);
    uint32_t u; memcpy(&u, &p, 4); return u;
}

// exact 3-way bf16 split of a pair of fp32
__device__ __forceinline__ void split_pair(float v0, float v1,
                                           uint32_t& H, uint32_t& M, uint32_t& L) {
    H = bf16pair(v0, v1);
    float h0 = __uint_as_float(H << 16);
    float h1 = __uint_as_float(H & 0xffff0000u);
    float r0 = v0 - h0, r1 = v1 - h1;          // exact
    M = bf16pair(r0, r1);
    float m0 = __uint_as_float(M << 16);
    float m1 = __uint_as_float(M & 0xffff0000u);
    L = bf16pair(r0 - m0, r1 - m1);
}

__device__ __forceinline__ void mma_bf16(float* d, const uint32_t* a, const uint32_t* b) {
    asm volatile(
        "mma.sync.aligned.m16n8k16.row.col.f32.bf16.bf16.f32 "
        "{%0,%1,%2,%3}, {%4,%5,%6,%7}, {%8,%9}, {%0,%1,%2,%3};"
        : "+f"(d[0]), "+f"(d[1]), "+f"(d[2]), "+f"(d[3])
        : "r"(a[0]), "r"(a[1]), "r"(a[2]), "r"(a[3]), "r"(b[0]), "r"(b[1]));
}

__device__ __forceinline__ void ldsm_x4(uint32_t* r, uint32_t addr) {
    asm volatile("ldmatrix.sync.aligned.m8n8.x4.shared.b16 {%0,%1,%2,%3}, [%4];"
                 : "=r"(r[0]), "=r"(r[1]), "=r"(r[2]), "=r"(r[3]) : "r"(addr));
}

__global__ __launch_bounds__(THREADS, 1)
void router_bf16x3_ldsm_kernel(const float* __restrict__ x,
                               const float* __restrict__ W,
                               const float* __restrict__ b,
                               float* __restrict__ out,
                               int n_tokens)
{
    extern __shared__ float s[];
    const uint32_t sb = smem_u32(s);
    const int tid  = threadIdx.x;
    const int lane = tid & 31;
    const int wid  = tid >> 5;          // 0..15
    const int g    = lane >> 2;
    const int tg   = lane & 3;
    const int m_base = (wid & 3) * 32;
    const int n_base = (wid >> 2) * 16;
    const int tok_base = blockIdx.x * TM;

    if (tid < NE) s[BIAS + tid] = b[tid];

    // accumulators: [mi][ni][4]
    float accM[2][2][4], accS[2][2][4];
#pragma unroll
    for (int mi = 0; mi < 2; mi++)
#pragma unroll
        for (int ni = 0; ni < 2; ni++)
#pragma unroll
            for (int j = 0; j < 4; j++) { accM[mi][ni][j] = 0.f; accS[mi][ni][j] = 0.f; }

    // ldmatrix per-lane base addresses (bytes), comp/mi/kk/buffer offsets added later
    // A octet t = lane>>3: t0:(r+0,k+0) t1:(r+8,k+0) t2:(r+0,k+16B) t3:(r+8,k+16B)
    const int rowA = (lane & 7) + ((lane >> 3) & 1) * 8;
    const int kselA = ((lane >> 4) & 1) * 16;
    const uint32_t aBase = sb + (uint32_t)(m_base + rowA) * (SROW * 4) + kselA;
    // B octet t: t0:(n+0,k+0) t1:(n+0,k+16B) t2:(n+8,k+0) t3:(n+8,k+16B)
    const int rowB = (lane & 7) + ((lane >> 4) & 1) * 8;
    const int kselB = ((lane >> 3) & 1) * 16;
    const uint32_t bBase = sb + (uint32_t)(n_base + rowB) * (SROW * 4) + kselB;

    // loader mapping: x groups of 8 fp32: 512 groups, 1/thread; W: 256 groups, tid<256
    const int xrow = tid >> 2, xkg = tid & 3;
    const int wrow = tid >> 2, wkg = tid & 3;   // valid for tid<256
    const float* xp = x + (size_t)(tok_base + xrow) * D_MODEL + xkg * 8;
    const float* wp = W + (size_t)wrow * D_MODEL + wkg * 8;
    const int xo = xrow * SROW + xkg * 4;
    const int wo = wrow * SROW + wkg * 4;

    float4 xr[2], wr[2];

    // ---- prologue: load + convert chunk 0 into buffer 0 ----
    {
        const float4* sx = reinterpret_cast<const float4*>(xp);
        xr[0] = sx[0]; xr[1] = sx[1];
        if (tid < 256) {
            const float4* sw = reinterpret_cast<const float4*>(wp);
            wr[0] = sw[0]; wr[1] = sw[1];
        }
        float* buf = s + TILE0;
        {
            float v[8] = {xr[0].x, xr[0].y, xr[0].z, xr[0].w,
                          xr[1].x, xr[1].y, xr[1].z, xr[1].w};
            uint32_t H[4], M[4], L[4];
#pragma unroll
            for (int j = 0; j < 4; j++) split_pair(v[2*j], v[2*j+1], H[j], M[j], L[j]);
            *reinterpret_cast<uint4*>(&buf[T_XH + xo]) = make_uint4(H[0], H[1], H[2], H[3]);
            *reinterpret_cast<uint4*>(&buf[T_XM + xo]) = make_uint4(M[0], M[1], M[2], M[3]);
            *reinterpret_cast<uint4*>(&buf[T_XL + xo]) = make_uint4(L[0], L[1], L[2], L[3]);
        }
        if (tid < 256) {
            float v[8] = {wr[0].x, wr[0].y, wr[0].z, wr[0].w,
                          wr[1].x, wr[1].y, wr[1].z, wr[1].w};
            uint32_t H[4], M[4], L[4];
#pragma unroll
            for (int j = 0; j < 4; j++) split_pair(v[2*j], v[2*j+1], H[j], M[j], L[j]);
            *reinterpret_cast<uint4*>(&buf[T_WH + wo]) = make_uint4(H[0], H[1], H[2], H[3]);
            *reinterpret_cast<uint4*>(&buf[T_WM + wo]) = make_uint4(M[0], M[1], M[2], M[3]);
            *reinterpret_cast<uint4*>(&buf[T_WL + wo]) = make_uint4(L[0], L[1], L[2], L[3]);
        }
    }
    __syncthreads();

#pragma unroll 1
    for (int c = 0; c < NCHUNK; c++) {
        const uint32_t bufB = (uint32_t)((TILE0 + (c & 1) * TILE_FLOATS) * 4);
        float* bufn = s + TILE0 + ((c & 1) ^ 1) * TILE_FLOATS;
        const bool more = (c + 1 < NCHUNK);

        // ---- prefetch chunk c+1 ----
        if (more) {
            const int kc = (c + 1) * BK;
            const float4* sx = reinterpret_cast<const float4*>(xp + kc);
            xr[0] = sx[0]; xr[1] = sx[1];
            if (tid < 256) {
                const float4* sw = reinterpret_cast<const float4*>(wp + kc);
                wr[0] = sw[0]; wr[1] = sw[1];
            }
        }

        // ---- MMA on current buffer via ldmatrix: 2 k16-steps, 6 products ----
#pragma unroll
        for (int kk = 0; kk < 2; kk++) {
            const uint32_t kByte = (uint32_t)(kk * 32);
            uint32_t aH[2][4], aM[2][4], aL[2][4];
#pragma unroll
            for (int mi = 0; mi < 2; mi++) {
                uint32_t ao = aBase + bufB + (uint32_t)(mi * 16 * SROW * 4) + kByte;
                ldsm_x4(aH[mi], ao + T_XH * 4);
                ldsm_x4(aM[mi], ao + T_XM * 4);
                ldsm_x4(aL[mi], ao + T_XL * 4);
            }
            uint32_t bH[4], bM[4], bL[4];   // [ni0.b0, ni0.b1, ni1.b0, ni1.b1]
            {
                uint32_t bo = bBase + bufB + kByte;
                ldsm_x4(bH, bo + T_WH * 4);
                ldsm_x4(bM, bo + T_WM * 4);
                ldsm_x4(bL, bo + T_WL * 4);
            }
#pragma unroll
            for (int mi = 0; mi < 2; mi++)
#pragma unroll
                for (int ni = 0; ni < 2; ni++)
                    mma_bf16(accM[mi][ni], aH[mi], bH + 2 * ni);
#pragma unroll
            for (int mi = 0; mi < 2; mi++)
#pragma unroll
                for (int ni = 0; ni < 2; ni++)
                    mma_bf16(accS[mi][ni], aH[mi], bM + 2 * ni);
#pragma unroll
            for (int mi = 0; mi < 2; mi++)
#pragma unroll
                for (int ni = 0; ni < 2; ni++)
                    mma_bf16(accS[mi][ni], aM[mi], bH + 2 * ni);
#pragma unroll
            for (int mi = 0; mi < 2; mi++)
#pragma unroll
                for (int ni = 0; ni < 2; ni++)
                    mma_bf16(accS[mi][ni], aM[mi], bM + 2 * ni);
#pragma unroll
            for (int mi = 0; mi < 2; mi++)
#pragma unroll
                for (int ni = 0; ni < 2; ni++)
                    mma_bf16(accS[mi][ni], aH[mi], bL + 2 * ni);
#pragma unroll
            for (int mi = 0; mi < 2; mi++)
#pragma unroll
                for (int ni = 0; ni < 2; ni++)
                    mma_bf16(accS[mi][ni], aL[mi], bH + 2 * ni);
        }

        // ---- convert chunk c+1 into next buffer ----
        if (more) {
            {
                float v[8] = {xr[0].x, xr[0].y, xr[0].z, xr[0].w,
                              xr[1].x, xr[1].y, xr[1].z, xr[1].w};
                uint32_t H[4], M[4], L[4];
#pragma unroll
                for (int j = 0; j < 4; j++) split_pair(v[2*j], v[2*j+1], H[j], M[j], L[j]);
                *reinterpret_cast<uint4*>(&bufn[T_XH + xo]) = make_uint4(H[0], H[1], H[2], H[3]);
                *reinterpret_cast<uint4*>(&bufn[T_XM + xo]) = make_uint4(M[0], M[1], M[2], M[3]);
                *reinterpret_cast<uint4*>(&bufn[T_XL + xo]) = make_uint4(L[0], L[1], L[2], L[3]);
            }
            if (tid < 256) {
                float v[8] = {wr[0].x, wr[0].y, wr[0].z, wr[0].w,
                              wr[1].x, wr[1].y, wr[1].z, wr[1].w};
                uint32_t H[4], M[4], L[4];
#pragma unroll
                for (int j = 0; j < 4; j++) split_pair(v[2*j], v[2*j+1], H[j], M[j], L[j]);
                *reinterpret_cast<uint4*>(&bufn[T_WH + wo]) = make_uint4(H[0], H[1], H[2], H[3]);
                *reinterpret_cast<uint4*>(&bufn[T_WM + wo]) = make_uint4(M[0], M[1], M[2], M[3]);
                *reinterpret_cast<uint4*>(&bufn[T_WL + wo]) = make_uint4(L[0], L[1], L[2], L[3]);
            }
        }
        __syncthreads();
    }

    // ---- combine accs (IEEE), dump logits ----
#pragma unroll
    for (int mi = 0; mi < 2; mi++)
#pragma unroll
        for (int ni = 0; ni < 2; ni++) {
            int r0 = m_base + mi * 16 + g;
            int c0 = n_base + ni * 8 + 2 * tg;
            s[LS + r0 * LS_STRIDE + c0]           = accM[mi][ni][0] + accS[mi][ni][0];
            s[LS + r0 * LS_STRIDE + c0 + 1]       = accM[mi][ni][1] + accS[mi][ni][1];
            s[LS + (r0 + 8) * LS_STRIDE + c0]     = accM[mi][ni][2] + accS[mi][ni][2];
            s[LS + (r0 + 8) * LS_STRIDE + c0 + 1] = accM[mi][ni][3] + accS[mi][ni][3];
        }
    __syncthreads();

    // ---- softmax + top-2 ----
    if (tid < TM) {
        const float* row = &s[LS + tid * LS_STRIDE];
        const float* bs  = &s[BIAS];
        float logit[64];
#pragma unroll
        for (int e = 0; e < 64; e++) logit[e] = row[e] + bs[e];

        float m1 = -1e30f, m2 = -1e30f;
        int i1 = 0, i2 = 0;
#pragma unroll
        for (int e = 0; e < 64; e++) {
            float v = logit[e];
            if (v > m1)      { m2 = m1; i2 = i1; m1 = v; i1 = e; }
            else if (v > m2) { m2 = v; i2 = e; }
        }
        float ssum = 0.f;
#pragma unroll
        for (int e = 0; e < 64; e++) ssum += __expf(logit[e] - m1);
        float inv = 1.0f / ssum;

        int gt = tok_base + tid;
        int ow = 2 * n_tokens;
        out[2 * gt + 0] = (float)i1;
        out[2 * gt + 1] = (float)i2;
        out[ow + 2 * gt + 0] = inv;
        out[ow + 2 * gt + 1] = __expf(m2 - m1) * inv;
    }
}

extern "C" void kernel_launch(void* const* d_in, const int* in_sizes, int n_in,
                              void* d_out, int out_size)
{
    const float* x = (const float*)d_in[0];
    const float* W = (const float*)d_in[1];
    const float* b = (const float*)d_in[2];
    float* out = (float*)d_out;

    int n_tokens = in_sizes[0] / D_MODEL;   // 32768
    cudaFuncSetAttribute(router_bf16x3_ldsm_kernel,
                         cudaFuncAttributeMaxDynamicSharedMemorySize, SMEM_BYTES);
    dim3 grid(n_tokens / TM);               // 256 CTAs
    router_bf16x3_ldsm_kernel<<<grid, THREADS, SMEM_BYTES>>>(x, W, b, out, n_tokens);
}